// round 11
// baseline (speedup 1.0000x reference)
#include <cuda_runtime.h>
#include <cuda_fp16.h>
#include <cstdint>

// Problem dims (fixed by reference setup_inputs)
#define BB   64
#define NN   1024
#define EE   8
#define OO   32
#define II   64
#define EO   256
#define NEO  (NN*EO)
#define CH   16

// ---------------------------------------------------------------------------
// Scratch (device globals; no allocation allowed)
// ---------------------------------------------------------------------------
__device__ __half g_u_hat[(size_t)BB * NN * EO];   // 32 MB [b][n][eo]
__device__ float  g_spart[CH * BB * EO];           // 1 MB  [chunk][b][eo]
__device__ float  g_b[BB * NN * EE];               // logits [b][n][e]

// ---------------------------------------------------------------------------
// PTX helpers (sm_90-level only; tcgen05 rejected by this harness's target)
// ---------------------------------------------------------------------------
__device__ __forceinline__ uint32_t smem_u32(const void* p) {
    uint32_t a;
    asm("{ .reg .u64 t; cvta.to.shared.u64 t, %1; cvt.u32.u64 %0, t; }"
        : "=r"(a) : "l"(p));
    return a;
}
#define MBAR_INIT(a, c) \
    asm volatile("mbarrier.init.shared.b64 [%0], %1;" :: "r"(a), "r"(c) : "memory")
#define MBAR_EXPECT(a, bytes) \
    asm volatile("mbarrier.arrive.expect_tx.shared.b64 _, [%0], %1;" \
                 :: "r"(a), "r"(bytes) : "memory")
#define BULK_G2S(dst, src, bytes, mbar) \
    asm volatile("cp.async.bulk.shared::cta.global.mbarrier::complete_tx::bytes " \
                 "[%0], [%1], %2, [%3];" \
                 :: "r"(dst), "l"(src), "r"(bytes), "r"(mbar) : "memory")
#define MBAR_WAIT(mbar, ph) do { \
    asm volatile("{\n\t.reg .pred P1;\n\tWL_%=:\n\t" \
        "mbarrier.try_wait.parity.acquire.cta.shared::cta.b64 P1, [%0], %1, 0x989680;\n\t" \
        "@P1 bra.uni WD_%=;\n\tbra.uni WL_%=;\n\tWD_%=:\n\t}" \
        :: "r"((uint32_t)(mbar)), "r"((uint32_t)(ph)) : "memory"); } while (0)

// fp32x2 packed FMA (PTX-only; ptxas never auto-fuses FFMA2)
__device__ __forceinline__ void ffma2(unsigned long long& d,
                                      unsigned long long a,
                                      unsigned long long b) {
    asm("fma.rn.f32x2 %0, %1, %2, %0;" : "+l"(d) : "l"(a), "l"(b));
}
__device__ __forceinline__ float2 asf2(unsigned long long v) {
    union { unsigned long long u; float2 f; } c; c.u = v; return c.f;
}
// pack two floats into f16x2 with `lo` in the low half (memory-first elem)
__device__ __forceinline__ unsigned pack_f16(float lo, float hi) {
    unsigned r;
    asm("cvt.rn.f16x2.f32 %0, %1, %2;" : "=r"(r) : "f"(hi), "f"(lo));
    return r;
}

// ---------------------------------------------------------------------------
// Kernel 1: u_hat[b,n,eo] = sum_i W[n,eo,i] * u[b,n,i]   (fp16 output)
// Round-6 FFMA2 kernel + k-half software pipeline:
//   fill(half0 + u) -> ldg(half1 into regs) -> sync -> compute(half0)
//   -> sts(half1) -> sync -> compute(half1) -> epilogue.
// ---------------------------------------------------------------------------
#define SW_FLOATS  (64*256)
#define SUD_FLOATS (64*128)
#define GEMM_SMEM_BYTES ((SW_FLOATS + SUD_FLOATS) * 4)

__global__ __launch_bounds__(256, 2)
void gemm_kernel(const float* __restrict__ u, const float* __restrict__ W) {
    extern __shared__ float smem[];
    float* sW  = smem;                 // [64][256] swizzled
    float* sUd = smem + SW_FLOATS;     // [64][128] dup'd

    const int n = blockIdx.x;
    const int t = threadIdx.x;
    const int w = t >> 5;
    const int l = t & 31;

    const float4* wg4 = (const float4*)(W + (size_t)n * (EO * II));

    // ---- fill sW half0 (k<32): per half, eo = idx>>3, kf4 = idx&7
    #pragma unroll
    for (int it = 0; it < 8; ++it) {
        int idx = t + it * 256;          // 0..2047
        int eo  = idx >> 3;
        int kf4 = idx & 7;
        float4 v = wg4[eo * 16 + kf4];
        int col  = eo ^ (kf4 << 2);
        float* p = &sW[(kf4 * 4) * 256 + col];
        p[0]   = v.x;
        p[256] = v.y;
        p[512] = v.z;
        p[768] = v.w;
    }
    // ---- fill sUd: duplicated pairs {u,u}
    {
        const int b  = t >> 2;
        const int fq = t & 3;
        const float4* ug4 = (const float4*)(u + ((size_t)b * NN + n) * II);
        float2* sUd2 = (float2*)sUd;
        #pragma unroll
        for (int i = 0; i < 4; ++i) {
            int f = fq * 4 + i;
            float4 v = ug4[f];
            int k0 = f * 4;
            sUd2[(k0 + 0) * 64 + b] = make_float2(v.x, v.x);
            sUd2[(k0 + 1) * 64 + b] = make_float2(v.y, v.y);
            sUd2[(k0 + 2) * 64 + b] = make_float2(v.z, v.z);
            sUd2[(k0 + 3) * 64 + b] = make_float2(v.w, v.w);
        }
    }
    // ---- issue half1 LDGs now; they fly across the barrier + compute(half0)
    float4 pend[8];
    #pragma unroll
    for (int it = 0; it < 8; ++it) {
        int idx = t + it * 256;
        int eo  = idx >> 3;
        int kf4 = idx & 7;
        pend[it] = wg4[eo * 16 + 8 + kf4];
    }
    __syncthreads();

    unsigned long long acc[8][4];
    #pragma unroll
    for (int r = 0; r < 8; ++r)
        #pragma unroll
        for (int p = 0; p < 4; ++p) acc[r][p] = 0ULL;

    const float* ubase = &sUd[w * 16];

    // ---- compute half0: k4 = 0..7
    #pragma unroll 4
    for (int k4 = 0; k4 < 8; ++k4) {
        const int X4 = (k4 & 7) << 2;
        const float* wbase = &sW[(4 * l) ^ X4];
        #pragma unroll
        for (int j = 0; j < 4; ++j) {
            const int k = k4 * 4 + j;
            const ulonglong2 w0 = *(const ulonglong2*)&wbase[k * 256];
            const ulonglong2 w1 = *(const ulonglong2*)&wbase[k * 256 + 128];
            const ulonglong2* ub = (const ulonglong2*)&ubase[k * 128];
            const ulonglong2 u0 = ub[0], u1 = ub[1], u2 = ub[2], u3 = ub[3];

            ffma2(acc[0][0], u0.x, w0.x); ffma2(acc[0][1], u0.x, w0.y);
            ffma2(acc[0][2], u0.x, w1.x); ffma2(acc[0][3], u0.x, w1.y);
            ffma2(acc[1][0], u0.y, w0.x); ffma2(acc[1][1], u0.y, w0.y);
            ffma2(acc[1][2], u0.y, w1.x); ffma2(acc[1][3], u0.y, w1.y);
            ffma2(acc[2][0], u1.x, w0.x); ffma2(acc[2][1], u1.x, w0.y);
            ffma2(acc[2][2], u1.x, w1.x); ffma2(acc[2][3], u1.x, w1.y);
            ffma2(acc[3][0], u1.y, w0.x); ffma2(acc[3][1], u1.y, w0.y);
            ffma2(acc[3][2], u1.y, w1.x); ffma2(acc[3][3], u1.y, w1.y);
            ffma2(acc[4][0], u2.x, w0.x); ffma2(acc[4][1], u2.x, w0.y);
            ffma2(acc[4][2], u2.x, w1.x); ffma2(acc[4][3], u2.x, w1.y);
            ffma2(acc[5][0], u2.y, w0.x); ffma2(acc[5][1], u2.y, w0.y);
            ffma2(acc[5][2], u2.y, w1.x); ffma2(acc[5][3], u2.y, w1.y);
            ffma2(acc[6][0], u3.x, w0.x); ffma2(acc[6][1], u3.x, w0.y);
            ffma2(acc[6][2], u3.x, w1.x); ffma2(acc[6][3], u3.x, w1.y);
            ffma2(acc[7][0], u3.y, w0.x); ffma2(acc[7][1], u3.y, w0.y);
            ffma2(acc[7][2], u3.y, w1.x); ffma2(acc[7][3], u3.y, w1.y);
        }
    }

    // ---- store half1 (k in [32,64)); region disjoint from half0 reads
    #pragma unroll
    for (int it = 0; it < 8; ++it) {
        int idx = t + it * 256;
        int eo  = idx >> 3;
        int kf4 = (idx & 7) + 8;
        int col = eo ^ ((kf4 & 7) << 2);
        float* p = &sW[(kf4 * 4) * 256 + col];
        p[0]   = pend[it].x;
        p[256] = pend[it].y;
        p[512] = pend[it].z;
        p[768] = pend[it].w;
    }
    __syncthreads();

    // ---- compute half1: k4 = 8..15
    #pragma unroll 4
    for (int k4 = 8; k4 < 16; ++k4) {
        const int X4 = (k4 & 7) << 2;
        const float* wbase = &sW[(4 * l) ^ X4];
        #pragma unroll
        for (int j = 0; j < 4; ++j) {
            const int k = k4 * 4 + j;
            const ulonglong2 w0 = *(const ulonglong2*)&wbase[k * 256];
            const ulonglong2 w1 = *(const ulonglong2*)&wbase[k * 256 + 128];
            const ulonglong2* ub = (const ulonglong2*)&ubase[k * 128];
            const ulonglong2 u0 = ub[0], u1 = ub[1], u2 = ub[2], u3 = ub[3];

            ffma2(acc[0][0], u0.x, w0.x); ffma2(acc[0][1], u0.x, w0.y);
            ffma2(acc[0][2], u0.x, w1.x); ffma2(acc[0][3], u0.x, w1.y);
            ffma2(acc[1][0], u0.y, w0.x); ffma2(acc[1][1], u0.y, w0.y);
            ffma2(acc[1][2], u0.y, w1.x); ffma2(acc[1][3], u0.y, w1.y);
            ffma2(acc[2][0], u1.x, w0.x); ffma2(acc[2][1], u1.x, w0.y);
            ffma2(acc[2][2], u1.x, w1.x); ffma2(acc[2][3], u1.x, w1.y);
            ffma2(acc[3][0], u1.y, w0.x); ffma2(acc[3][1], u1.y, w0.y);
            ffma2(acc[3][2], u1.y, w1.x); ffma2(acc[3][3], u1.y, w1.y);
            ffma2(acc[4][0], u2.x, w0.x); ffma2(acc[4][1], u2.x, w0.y);
            ffma2(acc[4][2], u2.x, w1.x); ffma2(acc[4][3], u2.x, w1.y);
            ffma2(acc[5][0], u2.y, w0.x); ffma2(acc[5][1], u2.y, w0.y);
            ffma2(acc[5][2], u2.y, w1.x); ffma2(acc[5][3], u2.y, w1.y);
            ffma2(acc[6][0], u3.x, w0.x); ffma2(acc[6][1], u3.x, w0.y);
            ffma2(acc[6][2], u3.x, w1.x); ffma2(acc[6][3], u3.x, w1.y);
            ffma2(acc[7][0], u3.y, w0.x); ffma2(acc[7][1], u3.y, w0.y);
            ffma2(acc[7][2], u3.y, w1.x); ffma2(acc[7][3], u3.y, w1.y);
        }
    }

    // ---- epilogue: fp16 stores; lane writes eo 4l..4l+3 and +128, coalesced
    __half* outp = g_u_hat + (size_t)n * EO + 4 * l;
    #pragma unroll
    for (int r = 0; r < 8; ++r) {
        float2 p0 = asf2(acc[r][0]), p1 = asf2(acc[r][1]);
        float2 p2 = asf2(acc[r][2]), p3 = asf2(acc[r][3]);
        __half* pp = outp + (size_t)(w * 8 + r) * NEO;
        uint2 lo, hi;
        lo.x = pack_f16(p0.x, p0.y); lo.y = pack_f16(p1.x, p1.y);
        hi.x = pack_f16(p2.x, p2.y); hi.y = pack_f16(p3.x, p3.y);
        *(uint2*)pp         = lo;
        *(uint2*)(pp + 128) = hi;
    }
}

// ---------------------------------------------------------------------------
// Kernel 2: s0 partial via TMA bulk staging (proven, ~4us).
// ---------------------------------------------------------------------------
__global__ __launch_bounds__(256)
void reduce_s0_kernel() {
    __shared__ __align__(128) char s_tile[64 * 512];
    __shared__ float s_sh[8 * EO];
    __shared__ __align__(8) uint64_t s_mbar;
    const int b = blockIdx.x >> 4;
    const int chunk = blockIdx.x & 15;
    const int t = threadIdx.x, w = t >> 5, l = t & 31;
    const uint32_t mbar = smem_u32(&s_mbar);

    if (t == 0) MBAR_INIT(mbar, 1);
    __syncthreads();
    if (t == 0) {
        const __half* gp = g_u_hat + (size_t)b * NEO + (size_t)(chunk * 64) * EO;
        uint64_t ga = (uint64_t)__cvta_generic_to_global((void*)gp);
        MBAR_EXPECT(mbar, 32768);
        BULK_G2S(smem_u32(s_tile), ga, 32768, mbar);
    }
    MBAR_WAIT(mbar, 0);

    float acc[8];
    #pragma unroll
    for (int i = 0; i < 8; ++i) acc[i] = 0.f;
    #pragma unroll
    for (int j = 0; j < 8; ++j) {
        uint4 r = *(const uint4*)(s_tile + (w * 8 + j) * 512 + l * 16);
        float2 f;
        f = __half22float2(*(const __half2*)&r.x); acc[0] += f.x; acc[1] += f.y;
        f = __half22float2(*(const __half2*)&r.y); acc[2] += f.x; acc[3] += f.y;
        f = __half22float2(*(const __half2*)&r.z); acc[4] += f.x; acc[5] += f.y;
        f = __half22float2(*(const __half2*)&r.w); acc[6] += f.x; acc[7] += f.y;
    }
    float* sw = &s_sh[w * EO + 8 * l];
    #pragma unroll
    for (int i = 0; i < 8; ++i) sw[i] = acc[i];
    __syncthreads();
    float sum = 0.f;
    #pragma unroll
    for (int ww = 0; ww < 8; ++ww) sum += s_sh[ww * EO + t];
    g_spart[chunk * (BB * EO) + b * EO + t] = sum * 0.125f;
}

// ---------------------------------------------------------------------------
// Kernel 3 (final): squash partial sums -> d_out
// ---------------------------------------------------------------------------
__global__ __launch_bounds__(256)
void squash_final_kernel(float* __restrict__ out) {
    const int t = threadIdx.x, w = t >> 5, l = t & 31;
    const int idx = (blockIdx.x * 8 + w) * 32 + l;
    float x = 0.f;
    #pragma unroll
    for (int c = 0; c < CH; ++c) x += g_spart[c * (BB * EO) + idx];
    float n2 = x * x;
    n2 += __shfl_xor_sync(0xffffffffu, n2, 1);
    n2 += __shfl_xor_sync(0xffffffffu, n2, 2);
    n2 += __shfl_xor_sync(0xffffffffu, n2, 4);
    n2 += __shfl_xor_sync(0xffffffffu, n2, 8);
    n2 += __shfl_xor_sync(0xffffffffu, n2, 16);
    float nrm = sqrtf(n2);
    float scale = n2 / ((1.f + n2) * (nrm + 1e-8f));
    out[idx] = x * scale;
}

// ---------------------------------------------------------------------------
// Kernel 4/5: shuffle-light routing iteration (round-9, measured 13.3us).
// ---------------------------------------------------------------------------
template <int ITER>
__global__ __launch_bounds__(256)
void routing_kernel() {
    __shared__ __align__(128) char s_tile[64 * 512];   // 32 KB
    __shared__ float s_v[EO];
    __shared__ float s_c[64 * 8];
    __shared__ float s_ph[2 * EO];
    __shared__ __align__(8) uint64_t s_mbar;
    const int b = blockIdx.x >> 4;
    const int chunk = blockIdx.x & 15;
    const int t = threadIdx.x, w = t >> 5, l = t & 31;
    const int e  = l & 7;
    const int nq = l >> 3;
    const uint32_t mbar = smem_u32(&s_mbar);

    if (t == 0) MBAR_INIT(mbar, 1);
    __syncthreads();
    if (t == 0) {
        const __half* gp = g_u_hat + (size_t)b * NEO + (size_t)(chunk * 64) * EO;
        uint64_t ga = (uint64_t)__cvta_generic_to_global((void*)gp);
        MBAR_EXPECT(mbar, 32768);
        BULK_G2S(smem_u32(s_tile), ga, 32768, mbar);
    }

    float* gb = g_b + b * (NN * EE) + (chunk * 64) * EE;
    float bpre[2];
    if (ITER == 2) {
        #pragma unroll
        for (int r = 0; r < 2; ++r)
            bpre[r] = gb[(w * 8 + r * 4 + nq) * 8 + e];
    }

    // prologue: v = squash(sum_c spart)  (overlaps TMA)
    {
        float x = 0.f;
        #pragma unroll
        for (int c = 0; c < CH; ++c) x += g_spart[c * (BB * EO) + b * EO + t];
        float n2 = x * x;
        n2 += __shfl_xor_sync(0xffffffffu, n2, 1);
        n2 += __shfl_xor_sync(0xffffffffu, n2, 2);
        n2 += __shfl_xor_sync(0xffffffffu, n2, 4);
        n2 += __shfl_xor_sync(0xffffffffu, n2, 8);
        n2 += __shfl_xor_sync(0xffffffffu, n2, 16);
        float nrm = sqrtf(n2);
        float scale = n2 / ((1.f + n2) * (nrm + 1e-8f));
        s_v[t] = x * scale;
    }
    __syncthreads();

    float vv[4][8];
    #pragma unroll
    for (int j = 0; j < 4; ++j) {
        const int jj = (j + e + (e >> 2)) & 3;
        const float* vp = s_v + e * 32 + jj * 8;
        float4 a = *(const float4*)vp;
        float4 bq = *(const float4*)(vp + 4);
        vv[j][0] = a.x;  vv[j][1] = a.y;  vv[j][2] = a.z;  vv[j][3] = a.w;
        vv[j][4] = bq.x; vv[j][5] = bq.y; vv[j][6] = bq.z; vv[j][7] = bq.w;
    }

    MBAR_WAIT(mbar, 0);

    // Phase A: dots + softmax + c
    #pragma unroll
    for (int r = 0; r < 2; ++r) {
        const int n = w * 8 + r * 4 + nq;
        const char* urow = s_tile + n * 512 + e * 64;
        float a0 = 0.f, a1 = 0.f;
        #pragma unroll
        for (int j = 0; j < 4; ++j) {
            const int jj = (j + e + (e >> 2)) & 3;
            uint4 q = *(const uint4*)(urow + jj * 16);
            float2 f;
            f = __half22float2(*(const __half2*)&q.x);
            a0 += f.x * vv[j][0]; a1 += f.y * vv[j][1];
            f = __half22float2(*(const __half2*)&q.y);
            a0 += f.x * vv[j][2]; a1 += f.y * vv[j][3];
            f = __half22float2(*(const __half2*)&q.z);
            a0 += f.x * vv[j][4]; a1 += f.y * vv[j][5];
            f = __half22float2(*(const __half2*)&q.w);
            a0 += f.x * vv[j][6]; a1 += f.y * vv[j][7];
        }
        float bn = a0 + a1;
        if (ITER == 2) bn += bpre[r];
        else gb[n * 8 + e] = bn;

        float m = bn;
        m = fmaxf(m, __shfl_xor_sync(0xffffffffu, m, 1));
        m = fmaxf(m, __shfl_xor_sync(0xffffffffu, m, 2));
        m = fmaxf(m, __shfl_xor_sync(0xffffffffu, m, 4));
        float ex = __expf(bn - m);
        float sm = ex;
        sm += __shfl_xor_sync(0xffffffffu, sm, 1);
        sm += __shfl_xor_sync(0xffffffffu, sm, 2);
        sm += __shfl_xor_sync(0xffffffffu, sm, 4);
        s_c[n * 8 + e] = __fdividef(ex, sm);
    }
    __syncthreads();

    // Phase B: s[eo] = sum_n c[n][e] * u_hat[n][eo]
    {
        const int h = t >> 7;
        const int p = t & 127;
        float ax = 0.f, ay = 0.f;
        const char* base = s_tile + (h * 32) * 512 + p * 4;
        const float* cp = s_c + (h * 32) * 8 + (p >> 4);
        #pragma unroll 8
        for (int i = 0; i < 32; ++i) {
            float2 f = __half22float2(*(const __half2*)(base + i * 512));
            float c = cp[i * 8];
            ax += c * f.x;
            ay += c * f.y;
        }
        s_ph[h * EO + 2 * p]     = ax;
        s_ph[h * EO + 2 * p + 1] = ay;
    }
    __syncthreads();
    g_spart[chunk * (BB * EO) + b * EO + t] = s_ph[t] + s_ph[EO + t];
}

// ---------------------------------------------------------------------------
// Launch
// ---------------------------------------------------------------------------
extern "C" void kernel_launch(void* const* d_in, const int* in_sizes, int n_in,
                              void* d_out, int out_size) {
    const float* u = (const float*)d_in[0];
    const float* W = (const float*)d_in[1];
    if (n_in >= 2 && in_sizes[0] > in_sizes[1]) {  // u = 4.19M elems, W = 16.78M
        const float* tmp = u; u = W; W = tmp;
    }
    float* out = (float*)d_out;
    (void)out_size;

    cudaFuncSetAttribute(gemm_kernel,
                         cudaFuncAttributeMaxDynamicSharedMemorySize,
                         GEMM_SMEM_BYTES);

    gemm_kernel<<<NN, 256, GEMM_SMEM_BYTES>>>(u, W);   // u_hat (fp16)
    reduce_s0_kernel<<<BB * CH, 256>>>();              // s0 partials (c=1/8)
    routing_kernel<1><<<BB * CH, 256>>>();             // v0, b1, s1
    routing_kernel<2><<<BB * CH, 256>>>();             // v1, b2, s2
    squash_final_kernel<<<64, 256>>>(out);             // v2 -> d_out
}

// round 13
// speedup vs baseline: 1.3969x; 1.3969x over previous
#include <cuda_runtime.h>
#include <cuda_fp16.h>
#include <cstdint>

// Problem dims (fixed by reference setup_inputs)
#define BB   64
#define NN   1024
#define EE   8
#define OO   32
#define II   64
#define EO   256
#define NEO  (NN*EO)
#define CH   16

// ---------------------------------------------------------------------------
// Scratch (device globals; no allocation allowed)
// ---------------------------------------------------------------------------
__device__ __half g_u_hat[(size_t)BB * NN * EO];   // 32 MB [b][n][eo]
__device__ float  g_spart[CH * BB * EO];           // 1 MB  [chunk][b][eo]
__device__ float  g_b[BB * NN * EE];               // logits [b][n][e]

// ---------------------------------------------------------------------------
// PTX helpers (sm_80/90-level; tcgen05 is rejected by this harness's target,
// but ldmatrix + mma.sync HMMA are standard and supported)
// ---------------------------------------------------------------------------
__device__ __forceinline__ uint32_t smem_u32(const void* p) {
    uint32_t a;
    asm("{ .reg .u64 t; cvta.to.shared.u64 t, %1; cvt.u32.u64 %0, t; }"
        : "=r"(a) : "l"(p));
    return a;
}
#define MBAR_INIT(a, c) \
    asm volatile("mbarrier.init.shared.b64 [%0], %1;" :: "r"(a), "r"(c) : "memory")
#define MBAR_EXPECT(a, bytes) \
    asm volatile("mbarrier.arrive.expect_tx.shared.b64 _, [%0], %1;" \
                 :: "r"(a), "r"(bytes) : "memory")
#define BULK_G2S(dst, src, bytes, mbar) \
    asm volatile("cp.async.bulk.shared::cta.global.mbarrier::complete_tx::bytes " \
                 "[%0], [%1], %2, [%3];" \
                 :: "r"(dst), "l"(src), "r"(bytes), "r"(mbar) : "memory")
#define MBAR_WAIT(mbar, ph) do { \
    asm volatile("{\n\t.reg .pred P1;\n\tWL_%=:\n\t" \
        "mbarrier.try_wait.parity.acquire.cta.shared::cta.b64 P1, [%0], %1, 0x989680;\n\t" \
        "@P1 bra.uni WD_%=;\n\tbra.uni WL_%=;\n\tWD_%=:\n\t}" \
        :: "r"((uint32_t)(mbar)), "r"((uint32_t)(ph)) : "memory"); } while (0)

// pack two floats into f16x2 with `lo` in the low half (memory-first elem)
__device__ __forceinline__ unsigned pack_f16(float lo, float hi) {
    unsigned r;
    asm("cvt.rn.f16x2.f32 %0, %1, %2;" : "=r"(r) : "f"(hi), "f"(lo));
    return r;
}
__device__ __forceinline__ void ldsm4(uint32_t* r, uint32_t addr) {
    asm volatile("ldmatrix.sync.aligned.m8n8.x4.shared.b16 {%0,%1,%2,%3}, [%4];"
                 : "=r"(r[0]), "=r"(r[1]), "=r"(r[2]), "=r"(r[3]) : "r"(addr));
}
__device__ __forceinline__ void mma16816(float* c, const uint32_t* a,
                                         uint32_t b0, uint32_t b1) {
    asm volatile(
        "mma.sync.aligned.m16n8k16.row.col.f32.f16.f16.f32 "
        "{%0,%1,%2,%3}, {%4,%5,%6,%7}, {%8,%9}, {%0,%1,%2,%3};"
        : "+f"(c[0]), "+f"(c[1]), "+f"(c[2]), "+f"(c[3])
        : "r"(a[0]), "r"(a[1]), "r"(a[2]), "r"(a[3]), "r"(b0), "r"(b1));
}

// ---------------------------------------------------------------------------
// Kernel 1: HMMA GEMM. One CTA per n, 256 threads (8 warps).
// D[eo,b] = Wh[eo,k] . (uh+ul)[b,k]^T, fp32 accum; 2-term precision split.
// SMEM tiles: [row][64k] fp16, 128B rows, 16B-unit swizzle u' = u ^ (row&7)
//  -> conflict-free ldmatrix. Warp w: eo tile [32w, 32w+32), all 64 b.
// Epilogue: frags -> padded [b][eo] bounce (528B rows) -> coalesced STG.
// ---------------------------------------------------------------------------
#define SM_W    0        // 256 x 128B = 32 KB (Wh) ; reused by bounce
#define SM_UH   32768    // 64 x 128B  =  8 KB
#define SM_UL   40960    // 64 x 128B  =  8 KB
#define SM_TOT  49152    // bounce needs 64*528 = 33792 <= 49152
#define BNC_ROW 528

__global__ __launch_bounds__(256, 2)
void gemm_kernel(const float* __restrict__ u, const float* __restrict__ W) {
    extern __shared__ __align__(128) char sm[];
    const uint32_t smb = smem_u32(sm);
    const int n = blockIdx.x;
    const int t = threadIdx.x;
    const int w = t >> 5;
    const int l = t & 31;

    // ---- fill Wh: coalesced float4 LDG -> fp16 8B swizzled STS
    {
        const float4* wg4 = (const float4*)(W + (size_t)n * (EO * II));
        #pragma unroll
        for (int it = 0; it < 16; ++it) {
            int idx = t + it * 256;          // 0..4095
            int eo  = idx >> 4;
            int kf4 = idx & 15;
            float4 v = wg4[idx];
            uint2 hp;
            hp.x = pack_f16(v.x, v.y);
            hp.y = pack_f16(v.z, v.w);
            uint32_t unit = (uint32_t)(kf4 >> 1) ^ (uint32_t)(eo & 7);
            *(uint2*)(sm + SM_W + eo * 128 + unit * 16 + (kf4 & 1) * 8) = hp;
        }
    }
    // ---- fill uh + ul (hi/lo fp16 split of fp32 u)
    {
        const float4* ug4 = (const float4*)u;
        #pragma unroll
        for (int it = 0; it < 4; ++it) {
            int idx = t + it * 256;          // 0..1023
            int b   = idx >> 4;
            int kf4 = idx & 15;
            float4 v = ug4[((size_t)b * NN + n) * 16 + kf4];
            __half h0 = __float2half_rn(v.x), h1 = __float2half_rn(v.y);
            __half h2 = __float2half_rn(v.z), h3 = __float2half_rn(v.w);
            uint2 hp, lp;
            hp.x = ((uint32_t)__half_as_ushort(h1) << 16) | __half_as_ushort(h0);
            hp.y = ((uint32_t)__half_as_ushort(h3) << 16) | __half_as_ushort(h2);
            lp.x = pack_f16(v.x - __half2float(h0), v.y - __half2float(h1));
            lp.y = pack_f16(v.z - __half2float(h2), v.w - __half2float(h3));
            uint32_t off = b * 128 + (((uint32_t)(kf4 >> 1) ^ (uint32_t)(b & 7)) * 16)
                         + (kf4 & 1) * 8;
            *(uint2*)(sm + SM_UH + off) = hp;
            *(uint2*)(sm + SM_UL + off) = lp;
        }
    }
    __syncthreads();

    float acc[2][8][4];
    #pragma unroll
    for (int i = 0; i < 2; ++i)
        #pragma unroll
        for (int j = 0; j < 8; ++j)
            #pragma unroll
            for (int k = 0; k < 4; ++k) acc[i][j][k] = 0.f;

    // ldmatrix lane-role decomposition (shared by A and B):
    //  row = base + (l&7) + ((l>>3)&1 or (l>>4))*8 per the x4 matrix order.
    #pragma unroll
    for (int ks = 0; ks < 4; ++ks) {
        uint32_t aF[2][4];
        #pragma unroll
        for (int mt = 0; mt < 2; ++mt) {
            uint32_t eoA = 32 * w + 16 * mt + (l & 7) + ((l >> 3) & 1) * 8;
            uint32_t k8  = 2 * ks + (l >> 4);
            ldsm4(aF[mt], smb + SM_W + eoA * 128 + ((k8 ^ (eoA & 7)) << 4));
        }
        #pragma unroll
        for (int np2 = 0; np2 < 4; ++np2) {
            uint32_t bB  = 16 * np2 + (l & 7) + ((l >> 4) << 3);
            uint32_t k8  = 2 * ks + ((l >> 3) & 1);
            uint32_t off = bB * 128 + ((k8 ^ (bB & 7)) << 4);
            uint32_t bh[4], bl[4];
            ldsm4(bh, smb + SM_UH + off);
            ldsm4(bl, smb + SM_UL + off);
            #pragma unroll
            for (int mt = 0; mt < 2; ++mt) {
                mma16816(acc[mt][2 * np2],     aF[mt], bh[0], bh[1]);
                mma16816(acc[mt][2 * np2],     aF[mt], bl[0], bl[1]);
                mma16816(acc[mt][2 * np2 + 1], aF[mt], bh[2], bh[3]);
                mma16816(acc[mt][2 * np2 + 1], aF[mt], bl[2], bl[3]);
            }
        }
    }
    __syncthreads();   // tiles dead; reuse SMEM as [b][eo] bounce (528B rows)

    // ---- bounce write: D frag (eo = 32w+16mt+(l>>2){+8}, b = 8np+2(l&3){+1})
    #pragma unroll
    for (int mt = 0; mt < 2; ++mt)
        #pragma unroll
        for (int np = 0; np < 8; ++np) {
            uint32_t eoD = 32 * w + 16 * mt + (l >> 2);
            uint32_t bD  = 8 * np + 2 * (l & 3);
            *(__half*)(sm + bD * BNC_ROW + eoD * 2)             = __float2half_rn(acc[mt][np][0]);
            *(__half*)(sm + (bD + 1) * BNC_ROW + eoD * 2)       = __float2half_rn(acc[mt][np][1]);
            *(__half*)(sm + bD * BNC_ROW + (eoD + 8) * 2)       = __float2half_rn(acc[mt][np][2]);
            *(__half*)(sm + (bD + 1) * BNC_ROW + (eoD + 8) * 2) = __float2half_rn(acc[mt][np][3]);
        }
    __syncthreads();

    // ---- global store: thread (b = t>>2, q = t&3) writes 64 eo (128B)
    {
        const int b = t >> 2, q = t & 3;
        __half* gp = g_u_hat + (size_t)b * NEO + (size_t)n * EO + q * 64;
        #pragma unroll
        for (int j = 0; j < 8; ++j) {
            uint4 v = *(const uint4*)(sm + b * BNC_ROW + q * 128 + j * 16);
            ((uint4*)gp)[j] = v;
        }
    }
}

// ---------------------------------------------------------------------------
// Kernel 2: s0 partial via TMA bulk staging (proven, ~4us).
// ---------------------------------------------------------------------------
__global__ __launch_bounds__(256)
void reduce_s0_kernel() {
    __shared__ __align__(128) char s_tile[64 * 512];
    __shared__ float s_sh[8 * EO];
    __shared__ __align__(8) uint64_t s_mbar;
    const int b = blockIdx.x >> 4;
    const int chunk = blockIdx.x & 15;
    const int t = threadIdx.x, w = t >> 5, l = t & 31;
    const uint32_t mbar = smem_u32(&s_mbar);

    if (t == 0) MBAR_INIT(mbar, 1);
    __syncthreads();
    if (t == 0) {
        const __half* gp = g_u_hat + (size_t)b * NEO + (size_t)(chunk * 64) * EO;
        uint64_t ga = (uint64_t)__cvta_generic_to_global((void*)gp);
        MBAR_EXPECT(mbar, 32768);
        BULK_G2S(smem_u32(s_tile), ga, 32768, mbar);
    }
    MBAR_WAIT(mbar, 0);

    float acc[8];
    #pragma unroll
    for (int i = 0; i < 8; ++i) acc[i] = 0.f;
    #pragma unroll
    for (int j = 0; j < 8; ++j) {
        uint4 r = *(const uint4*)(s_tile + (w * 8 + j) * 512 + l * 16);
        float2 f;
        f = __half22float2(*(const __half2*)&r.x); acc[0] += f.x; acc[1] += f.y;
        f = __half22float2(*(const __half2*)&r.y); acc[2] += f.x; acc[3] += f.y;
        f = __half22float2(*(const __half2*)&r.z); acc[4] += f.x; acc[5] += f.y;
        f = __half22float2(*(const __half2*)&r.w); acc[6] += f.x; acc[7] += f.y;
    }
    float* sw = &s_sh[w * EO + 8 * l];
    #pragma unroll
    for (int i = 0; i < 8; ++i) sw[i] = acc[i];
    __syncthreads();
    float sum = 0.f;
    #pragma unroll
    for (int ww = 0; ww < 8; ++ww) sum += s_sh[ww * EO + t];
    g_spart[chunk * (BB * EO) + b * EO + t] = sum * 0.125f;
}

// ---------------------------------------------------------------------------
// Kernel 3 (final): squash partial sums -> d_out
// ---------------------------------------------------------------------------
__global__ __launch_bounds__(256)
void squash_final_kernel(float* __restrict__ out) {
    const int t = threadIdx.x, w = t >> 5, l = t & 31;
    const int idx = (blockIdx.x * 8 + w) * 32 + l;
    float x = 0.f;
    #pragma unroll
    for (int c = 0; c < CH; ++c) x += g_spart[c * (BB * EO) + idx];
    float n2 = x * x;
    n2 += __shfl_xor_sync(0xffffffffu, n2, 1);
    n2 += __shfl_xor_sync(0xffffffffu, n2, 2);
    n2 += __shfl_xor_sync(0xffffffffu, n2, 4);
    n2 += __shfl_xor_sync(0xffffffffu, n2, 8);
    n2 += __shfl_xor_sync(0xffffffffu, n2, 16);
    float nrm = sqrtf(n2);
    float scale = n2 / ((1.f + n2) * (nrm + 1e-8f));
    out[idx] = x * scale;
}

// ---------------------------------------------------------------------------
// Kernel 4/5: shuffle-light routing iteration (round-9, measured 13.1-13.3us).
// ---------------------------------------------------------------------------
template <int ITER>
__global__ __launch_bounds__(256)
void routing_kernel() {
    __shared__ __align__(128) char s_tile[64 * 512];   // 32 KB
    __shared__ float s_v[EO];
    __shared__ float s_c[64 * 8];
    __shared__ float s_ph[2 * EO];
    __shared__ __align__(8) uint64_t s_mbar;
    const int b = blockIdx.x >> 4;
    const int chunk = blockIdx.x & 15;
    const int t = threadIdx.x, w = t >> 5, l = t & 31;
    const int e  = l & 7;
    const int nq = l >> 3;
    const uint32_t mbar = smem_u32(&s_mbar);

    if (t == 0) MBAR_INIT(mbar, 1);
    __syncthreads();
    if (t == 0) {
        const __half* gp = g_u_hat + (size_t)b * NEO + (size_t)(chunk * 64) * EO;
        uint64_t ga = (uint64_t)__cvta_generic_to_global((void*)gp);
        MBAR_EXPECT(mbar, 32768);
        BULK_G2S(smem_u32(s_tile), ga, 32768, mbar);
    }

    float* gb = g_b + b * (NN * EE) + (chunk * 64) * EE;
    float bpre[2];
    if (ITER == 2) {
        #pragma unroll
        for (int r = 0; r < 2; ++r)
            bpre[r] = gb[(w * 8 + r * 4 + nq) * 8 + e];
    }

    // prologue: v = squash(sum_c spart)  (overlaps TMA)
    {
        float x = 0.f;
        #pragma unroll
        for (int c = 0; c < CH; ++c) x += g_spart[c * (BB * EO) + b * EO + t];
        float n2 = x * x;
        n2 += __shfl_xor_sync(0xffffffffu, n2, 1);
        n2 += __shfl_xor_sync(0xffffffffu, n2, 2);
        n2 += __shfl_xor_sync(0xffffffffu, n2, 4);
        n2 += __shfl_xor_sync(0xffffffffu, n2, 8);
        n2 += __shfl_xor_sync(0xffffffffu, n2, 16);
        float nrm = sqrtf(n2);
        float scale = n2 / ((1.f + n2) * (nrm + 1e-8f));
        s_v[t] = x * scale;
    }
    __syncthreads();

    float vv[4][8];
    #pragma unroll
    for (int j = 0; j < 4; ++j) {
        const int jj = (j + e + (e >> 2)) & 3;
        const float* vp = s_v + e * 32 + jj * 8;
        float4 a = *(const float4*)vp;
        float4 bq = *(const float4*)(vp + 4);
        vv[j][0] = a.x;  vv[j][1] = a.y;  vv[j][2] = a.z;  vv[j][3] = a.w;
        vv[j][4] = bq.x; vv[j][5] = bq.y; vv[j][6] = bq.z; vv[j][7] = bq.w;
    }

    MBAR_WAIT(mbar, 0);

    // Phase A: dots + softmax + c
    #pragma unroll
    for (int r = 0; r < 2; ++r) {
        const int n = w * 8 + r * 4 + nq;
        const char* urow = s_tile + n * 512 + e * 64;
        float a0 = 0.f, a1 = 0.f;
        #pragma unroll
        for (int j = 0; j < 4; ++j) {
            const int jj = (j + e + (e >> 2)) & 3;
            uint4 q = *(const uint4*)(urow + jj * 16);
            float2 f;
            f = __half22float2(*(const __half2*)&q.x);
            a0 += f.x * vv[j][0]; a1 += f.y * vv[j][1];
            f = __half22float2(*(const __half2*)&q.y);
            a0 += f.x * vv[j][2]; a1 += f.y * vv[j][3];
            f = __half22float2(*(const __half2*)&q.z);
            a0 += f.x * vv[j][4]; a1 += f.y * vv[j][5];
            f = __half22float2(*(const __half2*)&q.w);
            a0 += f.x * vv[j][6]; a1 += f.y * vv[j][7];
        }
        float bn = a0 + a1;
        if (ITER == 2) bn += bpre[r];
        else gb[n * 8 + e] = bn;

        float m = bn;
        m = fmaxf(m, __shfl_xor_sync(0xffffffffu, m, 1));
        m = fmaxf(m, __shfl_xor_sync(0xffffffffu, m, 2));
        m = fmaxf(m, __shfl_xor_sync(0xffffffffu, m, 4));
        float ex = __expf(bn - m);
        float sm = ex;
        sm += __shfl_xor_sync(0xffffffffu, sm, 1);
        sm += __shfl_xor_sync(0xffffffffu, sm, 2);
        sm += __shfl_xor_sync(0xffffffffu, sm, 4);
        s_c[n * 8 + e] = __fdividef(ex, sm);
    }
    __syncthreads();

    // Phase B: s[eo] = sum_n c[n][e] * u_hat[n][eo]
    {
        const int h = t >> 7;
        const int p = t & 127;
        float ax = 0.f, ay = 0.f;
        const char* base = s_tile + (h * 32) * 512 + p * 4;
        const float* cp = s_c + (h * 32) * 8 + (p >> 4);
        #pragma unroll 8
        for (int i = 0; i < 32; ++i) {
            float2 f = __half22float2(*(const __half2*)(base + i * 512));
            float c = cp[i * 8];
            ax += c * f.x;
            ay += c * f.y;
        }
        s_ph[h * EO + 2 * p]     = ax;
        s_ph[h * EO + 2 * p + 1] = ay;
    }
    __syncthreads();
    g_spart[chunk * (BB * EO) + b * EO + t] = s_ph[t] + s_ph[EO + t];
}

// ---------------------------------------------------------------------------
// Launch
// ---------------------------------------------------------------------------
extern "C" void kernel_launch(void* const* d_in, const int* in_sizes, int n_in,
                              void* d_out, int out_size) {
    const float* u = (const float*)d_in[0];
    const float* W = (const float*)d_in[1];
    if (n_in >= 2 && in_sizes[0] > in_sizes[1]) {  // u = 4.19M elems, W = 16.78M
        const float* tmp = u; u = W; W = tmp;
    }
    float* out = (float*)d_out;
    (void)out_size;

    cudaFuncSetAttribute(gemm_kernel,
                         cudaFuncAttributeMaxDynamicSharedMemorySize, SM_TOT);

    gemm_kernel<<<NN, 256, SM_TOT>>>(u, W);            // u_hat (fp16, HMMA)
    reduce_s0_kernel<<<BB * CH, 256>>>();              // s0 partials (c=1/8)
    routing_kernel<1><<<BB * CH, 256>>>();             // v0, b1, s1
    routing_kernel<2><<<BB * CH, 256>>>();             // v1, b2, s2
    squash_final_kernel<<<64, 256>>>(out);             // v2 -> d_out
}

// round 17
// speedup vs baseline: 1.4548x; 1.0414x over previous
#include <cuda_runtime.h>
#include <cuda_fp16.h>
#include <cstdint>

// Problem dims (fixed by reference setup_inputs)
#define BB   64
#define NN   1024
#define EE   8
#define OO   32
#define II   64
#define EO   256
#define NEO  (NN*EO)
#define CH   16

// ---------------------------------------------------------------------------
// Scratch (device globals; no allocation allowed)
// ---------------------------------------------------------------------------
__device__ __half g_u_hat[(size_t)BB * NN * EO];   // 32 MB [b][n][eo]
__device__ float  g_spart[CH * BB * EO];           // 1 MB  [chunk][b][eo]
__device__ float  g_b[BB * NN * EE];               // logits [b][n][e]

// ---------------------------------------------------------------------------
// PTX helpers (sm_80/90-level; tcgen05 is rejected by this harness's target,
// but ldmatrix + mma.sync HMMA are standard and supported)
// ---------------------------------------------------------------------------
__device__ __forceinline__ uint32_t smem_u32(const void* p) {
    uint32_t a;
    asm("{ .reg .u64 t; cvta.to.shared.u64 t, %1; cvt.u32.u64 %0, t; }"
        : "=r"(a) : "l"(p));
    return a;
}
#define MBAR_INIT(a, c) \
    asm volatile("mbarrier.init.shared.b64 [%0], %1;" :: "r"(a), "r"(c) : "memory")
#define MBAR_EXPECT(a, bytes) \
    asm volatile("mbarrier.arrive.expect_tx.shared.b64 _, [%0], %1;" \
                 :: "r"(a), "r"(bytes) : "memory")
#define BULK_G2S(dst, src, bytes, mbar) \
    asm volatile("cp.async.bulk.shared::cta.global.mbarrier::complete_tx::bytes " \
                 "[%0], [%1], %2, [%3];" \
                 :: "r"(dst), "l"(src), "r"(bytes), "r"(mbar) : "memory")
#define MBAR_WAIT(mbar, ph) do { \
    asm volatile("{\n\t.reg .pred P1;\n\tWL_%=:\n\t" \
        "mbarrier.try_wait.parity.acquire.cta.shared::cta.b64 P1, [%0], %1, 0x989680;\n\t" \
        "@P1 bra.uni WD_%=;\n\tbra.uni WL_%=;\n\tWD_%=:\n\t}" \
        :: "r"((uint32_t)(mbar)), "r"((uint32_t)(ph)) : "memory"); } while (0)

// pack two floats into f16x2 with `lo` in the low half (memory-first elem)
__device__ __forceinline__ unsigned pack_f16(float lo, float hi) {
    unsigned r;
    asm("cvt.rn.f16x2.f32 %0, %1, %2;" : "=r"(r) : "f"(hi), "f"(lo));
    return r;
}
__device__ __forceinline__ void ldsm4(uint32_t* r, uint32_t addr) {
    asm volatile("ldmatrix.sync.aligned.m8n8.x4.shared.b16 {%0,%1,%2,%3}, [%4];"
                 : "=r"(r[0]), "=r"(r[1]), "=r"(r[2]), "=r"(r[3]) : "r"(addr));
}
__device__ __forceinline__ void mma16816(float* c, const uint32_t* a,
                                         uint32_t b0, uint32_t b1) {
    asm volatile(
        "mma.sync.aligned.m16n8k16.row.col.f32.f16.f16.f32 "
        "{%0,%1,%2,%3}, {%4,%5,%6,%7}, {%8,%9}, {%0,%1,%2,%3};"
        : "+f"(c[0]), "+f"(c[1]), "+f"(c[2]), "+f"(c[3])
        : "r"(a[0]), "r"(a[1]), "r"(a[2]), "r"(a[3]), "r"(b0), "r"(b1));
}

// ---------------------------------------------------------------------------
// Kernel 1: HMMA GEMM. TWO CTAs per n (half-eo split), grid 2048, 256 thr.
// CTA (n, half): D[eo=128, b=64] = Wh[eo,k].(uh+ul)[b,k]^T, fp32 accum.
// Warp w owns eo tile [16w, 16w+16) (local); acc 32 regs -> 4 CTAs/SM.
// SMEM tiles: [row][64k] fp16, 128B rows, swizzle unit ^= (row&7).
// Epilogue: frags -> padded [b][128eo] bounce (272B rows) -> coalesced STG.
// ---------------------------------------------------------------------------
#define SM_W    0        // 128 x 128B = 16 KB (Wh); region reused by bounce
#define SM_UH   18432    // 64 x 128B = 8 KB
#define SM_UL   26624    // 64 x 128B = 8 KB
#define SM_TOT  34816    // bounce needs 64*272 = 17408 <= 18432
#define BNC_ROW 272

__global__ __launch_bounds__(256, 4)
void gemm_kernel(const float* __restrict__ u, const float* __restrict__ W) {
    extern __shared__ __align__(128) char sm[];
    const uint32_t smb = smem_u32(sm);
    const int n = blockIdx.x >> 1;
    const int half = blockIdx.x & 1;
    const int t = threadIdx.x;
    const int w = t >> 5;
    const int l = t & 31;

    // ---- fill Wh (this half's 128 eo): coalesced float4 LDG -> swizzled STS
    {
        const float4* wg4 = (const float4*)(W + (size_t)n * (EO * II))
                          + (size_t)half * 128 * 16;
        #pragma unroll
        for (int it = 0; it < 8; ++it) {
            int idx = t + it * 256;          // 0..2047
            int eo  = idx >> 4;              // local 0..127
            int kf4 = idx & 15;
            float4 v = wg4[idx];
            uint2 hp;
            hp.x = pack_f16(v.x, v.y);
            hp.y = pack_f16(v.z, v.w);
            uint32_t unit = (uint32_t)(kf4 >> 1) ^ (uint32_t)(eo & 7);
            *(uint2*)(sm + SM_W + eo * 128 + unit * 16 + (kf4 & 1) * 8) = hp;
        }
    }
    // ---- fill uh + ul (hi/lo fp16 split of fp32 u)
    {
        const float4* ug4 = (const float4*)u;
        #pragma unroll
        for (int it = 0; it < 4; ++it) {
            int idx = t + it * 256;          // 0..1023
            int b   = idx >> 4;
            int kf4 = idx & 15;
            float4 v = ug4[((size_t)b * NN + n) * 16 + kf4];
            __half h0 = __float2half_rn(v.x), h1 = __float2half_rn(v.y);
            __half h2 = __float2half_rn(v.z), h3 = __float2half_rn(v.w);
            uint2 hp, lp;
            hp.x = ((uint32_t)__half_as_ushort(h1) << 16) | __half_as_ushort(h0);
            hp.y = ((uint32_t)__half_as_ushort(h3) << 16) | __half_as_ushort(h2);
            lp.x = pack_f16(v.x - __half2float(h0), v.y - __half2float(h1));
            lp.y = pack_f16(v.z - __half2float(h2), v.w - __half2float(h3));
            uint32_t off = b * 128 + (((uint32_t)(kf4 >> 1) ^ (uint32_t)(b & 7)) * 16)
                         + (kf4 & 1) * 8;
            *(uint2*)(sm + SM_UH + off) = hp;
            *(uint2*)(sm + SM_UL + off) = lp;
        }
    }
    __syncthreads();

    float acc[8][4];
    #pragma unroll
    for (int j = 0; j < 8; ++j)
        #pragma unroll
        for (int k = 0; k < 4; ++k) acc[j][k] = 0.f;

    #pragma unroll
    for (int ks = 0; ks < 4; ++ks) {
        uint32_t aF[4];
        {
            uint32_t eoA = 16 * w + (l & 7) + ((l >> 3) & 1) * 8;
            uint32_t k8  = 2 * ks + (l >> 4);
            ldsm4(aF, smb + SM_W + eoA * 128 + ((k8 ^ (eoA & 7)) << 4));
        }
        #pragma unroll
        for (int np2 = 0; np2 < 4; ++np2) {
            uint32_t bB  = 16 * np2 + (l & 7) + ((l >> 4) << 3);
            uint32_t k8  = 2 * ks + ((l >> 3) & 1);
            uint32_t off = bB * 128 + ((k8 ^ (bB & 7)) << 4);
            uint32_t bh[4], bl[4];
            ldsm4(bh, smb + SM_UH + off);
            ldsm4(bl, smb + SM_UL + off);
            mma16816(acc[2 * np2],     aF, bh[0], bh[1]);
            mma16816(acc[2 * np2],     aF, bl[0], bl[1]);
            mma16816(acc[2 * np2 + 1], aF, bh[2], bh[3]);
            mma16816(acc[2 * np2 + 1], aF, bl[2], bl[3]);
        }
    }
    __syncthreads();   // tiles dead; reuse W region as [b][128eo] bounce

    // ---- bounce write: D frag (eo = 16w+(l>>2){+8}, b = 8np+2(l&3){+1})
    #pragma unroll
    for (int np = 0; np < 8; ++np) {
        uint32_t eoD = 16 * w + (l >> 2);
        uint32_t bD  = 8 * np + 2 * (l & 3);
        *(__half*)(sm + bD * BNC_ROW + eoD * 2)             = __float2half_rn(acc[np][0]);
        *(__half*)(sm + (bD + 1) * BNC_ROW + eoD * 2)       = __float2half_rn(acc[np][1]);
        *(__half*)(sm + bD * BNC_ROW + (eoD + 8) * 2)       = __float2half_rn(acc[np][2]);
        *(__half*)(sm + (bD + 1) * BNC_ROW + (eoD + 8) * 2) = __float2half_rn(acc[np][3]);
    }
    __syncthreads();

    // ---- global store: thread (b = t>>2, q = t&3) writes 32 eo (64B)
    {
        const int b = t >> 2, q = t & 3;
        __half* gp = g_u_hat + (size_t)b * NEO + (size_t)n * EO
                   + half * 128 + q * 32;
        const char* sp = sm + b * BNC_ROW + q * 64;
        #pragma unroll
        for (int j = 0; j < 4; ++j)
            ((uint4*)gp)[j] = *(const uint4*)(sp + j * 16);
    }
}

// ---------------------------------------------------------------------------
// Kernel 2: s0 partial via TMA bulk staging (proven, ~4us).
// ---------------------------------------------------------------------------
__global__ __launch_bounds__(256)
void reduce_s0_kernel() {
    __shared__ __align__(128) char s_tile[64 * 512];
    __shared__ float s_sh[8 * EO];
    __shared__ __align__(8) uint64_t s_mbar;
    const int b = blockIdx.x >> 4;
    const int chunk = blockIdx.x & 15;
    const int t = threadIdx.x, w = t >> 5, l = t & 31;
    const uint32_t mbar = smem_u32(&s_mbar);

    if (t == 0) MBAR_INIT(mbar, 1);
    __syncthreads();
    if (t == 0) {
        const __half* gp = g_u_hat + (size_t)b * NEO + (size_t)(chunk * 64) * EO;
        uint64_t ga = (uint64_t)__cvta_generic_to_global((void*)gp);
        MBAR_EXPECT(mbar, 32768);
        BULK_G2S(smem_u32(s_tile), ga, 32768, mbar);
    }
    MBAR_WAIT(mbar, 0);

    float acc[8];
    #pragma unroll
    for (int i = 0; i < 8; ++i) acc[i] = 0.f;
    #pragma unroll
    for (int j = 0; j < 8; ++j) {
        uint4 r = *(const uint4*)(s_tile + (w * 8 + j) * 512 + l * 16);
        float2 f;
        f = __half22float2(*(const __half2*)&r.x); acc[0] += f.x; acc[1] += f.y;
        f = __half22float2(*(const __half2*)&r.y); acc[2] += f.x; acc[3] += f.y;
        f = __half22float2(*(const __half2*)&r.z); acc[4] += f.x; acc[5] += f.y;
        f = __half22float2(*(const __half2*)&r.w); acc[6] += f.x; acc[7] += f.y;
    }
    float* sw = &s_sh[w * EO + 8 * l];
    #pragma unroll
    for (int i = 0; i < 8; ++i) sw[i] = acc[i];
    __syncthreads();
    float sum = 0.f;
    #pragma unroll
    for (int ww = 0; ww < 8; ++ww) sum += s_sh[ww * EO + t];
    g_spart[chunk * (BB * EO) + b * EO + t] = sum * 0.125f;
}

// ---------------------------------------------------------------------------
// Kernel 3 (final): squash partial sums -> d_out
// ---------------------------------------------------------------------------
__global__ __launch_bounds__(256)
void squash_final_kernel(float* __restrict__ out) {
    const int t = threadIdx.x, w = t >> 5, l = t & 31;
    const int idx = (blockIdx.x * 8 + w) * 32 + l;
    float x = 0.f;
    #pragma unroll
    for (int c = 0; c < CH; ++c) x += g_spart[c * (BB * EO) + idx];
    float n2 = x * x;
    n2 += __shfl_xor_sync(0xffffffffu, n2, 1);
    n2 += __shfl_xor_sync(0xffffffffu, n2, 2);
    n2 += __shfl_xor_sync(0xffffffffu, n2, 4);
    n2 += __shfl_xor_sync(0xffffffffu, n2, 8);
    n2 += __shfl_xor_sync(0xffffffffu, n2, 16);
    float nrm = sqrtf(n2);
    float scale = n2 / ((1.f + n2) * (nrm + 1e-8f));
    out[idx] = x * scale;
}

// ---------------------------------------------------------------------------
// Kernel 4/5: shuffle-light routing iteration (round-9, measured 13.1-13.3us).
// ---------------------------------------------------------------------------
template <int ITER>
__global__ __launch_bounds__(256)
void routing_kernel() {
    __shared__ __align__(128) char s_tile[64 * 512];   // 32 KB
    __shared__ float s_v[EO];
    __shared__ float s_c[64 * 8];
    __shared__ float s_ph[2 * EO];
    __shared__ __align__(8) uint64_t s_mbar;
    const int b = blockIdx.x >> 4;
    const int chunk = blockIdx.x & 15;
    const int t = threadIdx.x, w = t >> 5, l = t & 31;
    const int e  = l & 7;
    const int nq = l >> 3;
    const uint32_t mbar = smem_u32(&s_mbar);

    if (t == 0) MBAR_INIT(mbar, 1);
    __syncthreads();
    if (t == 0) {
        const __half* gp = g_u_hat + (size_t)b * NEO + (size_t)(chunk * 64) * EO;
        uint64_t ga = (uint64_t)__cvta_generic_to_global((void*)gp);
        MBAR_EXPECT(mbar, 32768);
        BULK_G2S(smem_u32(s_tile), ga, 32768, mbar);
    }

    float* gb = g_b + b * (NN * EE) + (chunk * 64) * EE;
    float bpre[2];
    if (ITER == 2) {
        #pragma unroll
        for (int r = 0; r < 2; ++r)
            bpre[r] = gb[(w * 8 + r * 4 + nq) * 8 + e];
    }

    // prologue: v = squash(sum_c spart)  (overlaps TMA)
    {
        float x = 0.f;
        #pragma unroll
        for (int c = 0; c < CH; ++c) x += g_spart[c * (BB * EO) + b * EO + t];
        float n2 = x * x;
        n2 += __shfl_xor_sync(0xffffffffu, n2, 1);
        n2 += __shfl_xor_sync(0xffffffffu, n2, 2);
        n2 += __shfl_xor_sync(0xffffffffu, n2, 4);
        n2 += __shfl_xor_sync(0xffffffffu, n2, 8);
        n2 += __shfl_xor_sync(0xffffffffu, n2, 16);
        float nrm = sqrtf(n2);
        float scale = n2 / ((1.f + n2) * (nrm + 1e-8f));
        s_v[t] = x * scale;
    }
    __syncthreads();

    float vv[4][8];
    #pragma unroll
    for (int j = 0; j < 4; ++j) {
        const int jj = (j + e + (e >> 2)) & 3;
        const float* vp = s_v + e * 32 + jj * 8;
        float4 a = *(const float4*)vp;
        float4 bq = *(const float4*)(vp + 4);
        vv[j][0] = a.x;  vv[j][1] = a.y;  vv[j][2] = a.z;  vv[j][3] = a.w;
        vv[j][4] = bq.x; vv[j][5] = bq.y; vv[j][6] = bq.z; vv[j][7] = bq.w;
    }

    MBAR_WAIT(mbar, 0);

    // Phase A: dots + softmax + c
    #pragma unroll
    for (int r = 0; r < 2; ++r) {
        const int n = w * 8 + r * 4 + nq;
        const char* urow = s_tile + n * 512 + e * 64;
        float a0 = 0.f, a1 = 0.f;
        #pragma unroll
        for (int j = 0; j < 4; ++j) {
            const int jj = (j + e + (e >> 2)) & 3;
            uint4 q = *(const uint4*)(urow + jj * 16);
            float2 f;
            f = __half22float2(*(const __half2*)&q.x);
            a0 += f.x * vv[j][0]; a1 += f.y * vv[j][1];
            f = __half22float2(*(const __half2*)&q.y);
            a0 += f.x * vv[j][2]; a1 += f.y * vv[j][3];
            f = __half22float2(*(const __half2*)&q.z);
            a0 += f.x * vv[j][4]; a1 += f.y * vv[j][5];
            f = __half22float2(*(const __half2*)&q.w);
            a0 += f.x * vv[j][6]; a1 += f.y * vv[j][7];
        }
        float bn = a0 + a1;
        if (ITER == 2) bn += bpre[r];
        else gb[n * 8 + e] = bn;

        float m = bn;
        m = fmaxf(m, __shfl_xor_sync(0xffffffffu, m, 1));
        m = fmaxf(m, __shfl_xor_sync(0xffffffffu, m, 2));
        m = fmaxf(m, __shfl_xor_sync(0xffffffffu, m, 4));
        float ex = __expf(bn - m);
        float sm = ex;
        sm += __shfl_xor_sync(0xffffffffu, sm, 1);
        sm += __shfl_xor_sync(0xffffffffu, sm, 2);
        sm += __shfl_xor_sync(0xffffffffu, sm, 4);
        s_c[n * 8 + e] = __fdividef(ex, sm);
    }
    __syncthreads();

    // Phase B: s[eo] = sum_n c[n][e] * u_hat[n][eo]
    {
        const int h = t >> 7;
        const int p = t & 127;
        float ax = 0.f, ay = 0.f;
        const char* base = s_tile + (h * 32) * 512 + p * 4;
        const float* cp = s_c + (h * 32) * 8 + (p >> 4);
        #pragma unroll 8
        for (int i = 0; i < 32; ++i) {
            float2 f = __half22float2(*(const __half2*)(base + i * 512));
            float c = cp[i * 8];
            ax += c * f.x;
            ay += c * f.y;
        }
        s_ph[h * EO + 2 * p]     = ax;
        s_ph[h * EO + 2 * p + 1] = ay;
    }
    __syncthreads();
    g_spart[chunk * (BB * EO) + b * EO + t] = s_ph[t] + s_ph[EO + t];
}

// ---------------------------------------------------------------------------
// Launch
// ---------------------------------------------------------------------------
extern "C" void kernel_launch(void* const* d_in, const int* in_sizes, int n_in,
                              void* d_out, int out_size) {
    const float* u = (const float*)d_in[0];
    const float* W = (const float*)d_in[1];
    if (n_in >= 2 && in_sizes[0] > in_sizes[1]) {  // u = 4.19M elems, W = 16.78M
        const float* tmp = u; u = W; W = tmp;
    }
    float* out = (float*)d_out;
    (void)out_size;

    cudaFuncSetAttribute(gemm_kernel,
                         cudaFuncAttributeMaxDynamicSharedMemorySize, SM_TOT);

    gemm_kernel<<<2 * NN, 256, SM_TOT>>>(u, W);        // u_hat (fp16, HMMA)
    reduce_s0_kernel<<<BB * CH, 256>>>();              // s0 partials (c=1/8)
    routing_kernel<1><<<BB * CH, 256>>>();             // v0, b1, s1
    routing_kernel<2><<<BB * CH, 256>>>();             // v1, b2, s2
    squash_final_kernel<<<64, 256>>>(out);             // v2 -> d_out
}